// round 17
// baseline (speedup 1.0000x reference)
#include <cuda_runtime.h>
#include <cuda_fp16.h>
#include <cstdint>

#define BB   64
#define SS   1024
#define EE   128
#define HH   512
#define NTHR 256
#define NGRP 8         // batch groups (= clusters)
#define NCG  16        // CTAs per group (= cluster size)
#define NB   8         // batches per group
#define HPC  32        // h columns per CTA
#define MRR  128       // D rows per CTA = 4 gates x 32 h

// ---- rnn dynamic smem layout (bytes) ----
#define A_BYTES  (MRR * HH * 2)          // 131072 fp16 Wh tile (1024B rows, swizzled)
#define B_BYTES  (NB * HH * 2)           // 8192 fp16 H tile (1024B rows, swizzled)
#define B0_OFF   A_BYTES                 // double-buffered H tile
#define B1_OFF   (A_BYTES + B_BYTES)
#define WX_OFF   (A_BYTES + 2 * B_BYTES) // Wx tile [128 m][128 k] fp16, 256B rows
#define WX_BYTES (MRR * EE * 2)          // 32768
#define XS_OFF   (WX_OFF + WX_BYTES)     // X tile [8 b][128 k] fp16, 256B rows
#define XS_BYTES (NB * EE * 2)           // 2048
#define G_OFF    (XS_OFF + XS_BYTES)     // Gsm float[128][10]
#define G_BYTES  (MRR * 10 * 4)          // 5120
#define HN_OFF   (G_OFF + G_BYTES)       // HnSm half[8 b][40] (32 used, 80B/b)
#define HN_BYTES (NB * 40 * 2)           // 640
#define YS_OFF   (HN_OFF + HN_BYTES)     // Ysm float[32][10]
#define YS_BYTES (32 * 10 * 4)           // 1280
#define RNN_SMEM (YS_OFF + YS_BYTES)     // 189312

// ---------------- module-scope scratch ----------------
__device__ __align__(128) __half        g_Hbuf0[BB * HH];              // [b][h] fp16 (H0)
__device__ __align__(128) float         g_Cbuf[HH * BB];               // [h][b]
__device__ __align__(128) float         g_Hfin[HH * BB];               // [h][b]
__device__ __align__(128) float         g_weff[HH];
__device__ __align__(128) float         g_beff[1];
__device__ __align__(128) float         g_party[(size_t)NGRP * NCG * SS * NB];
__device__ __align__(128) unsigned char g_Abuf[(size_t)NCG * A_BYTES];    // Wh images (per cidx)
__device__ __align__(128) unsigned char g_Wxbuf[(size_t)NCG * WX_BYTES];  // Wx images (per cidx)

// fast activations
__device__ __forceinline__ float tanh_fast(float x) {
    float y;
    asm("tanh.approx.f32 %0, %1;" : "=f"(y) : "f"(x));
    return y;
}
__device__ __forceinline__ float sigf(float x)   { return fmaf(0.5f, tanh_fast(0.5f * x), 0.5f); }
__device__ __forceinline__ float tanhf_(float x) { return tanh_fast(x); }

__device__ __forceinline__ uint32_t smem_u32(const void* p) {
    uint32_t a;
    asm("{ .reg .u64 t; cvta.to.shared.u64 t, %1; cvt.u32.u64 %0, t; }" : "=r"(a) : "l"(p));
    return a;
}
__device__ __forceinline__ uint32_t cta_rank() {
    uint32_t r;
    asm("mov.u32 %0, %%cluster_ctarank;" : "=r"(r));
    return r;
}
__device__ __forceinline__ void ldsm4(uint32_t* r, uint32_t addr) {
    asm volatile("ldmatrix.sync.aligned.m8n8.x4.shared.b16 {%0,%1,%2,%3}, [%4];"
                 : "=r"(r[0]), "=r"(r[1]), "=r"(r[2]), "=r"(r[3]) : "r"(addr));
}
__device__ __forceinline__ void ldsm2(uint32_t* r, uint32_t addr) {
    asm volatile("ldmatrix.sync.aligned.m8n8.x2.shared.b16 {%0,%1}, [%2];"
                 : "=r"(r[0]), "=r"(r[1]) : "r"(addr));
}
__device__ __forceinline__ void mma16816(float* d, const uint32_t* a, const uint32_t* b) {
    asm volatile("mma.sync.aligned.m16n8k16.row.col.f32.f16.f16.f32 "
                 "{%0,%1,%2,%3}, {%4,%5,%6,%7}, {%8,%9}, {%0,%1,%2,%3};"
                 : "+f"(d[0]), "+f"(d[1]), "+f"(d[2]), "+f"(d[3])
                 : "r"(a[0]), "r"(a[1]), "r"(a[2]), "r"(a[3]), "r"(b[0]), "r"(b[1]));
}
__device__ __forceinline__ void dsmem_st16(uint32_t laddr, uint32_t rank, uint4 v) {
    asm volatile(
        "{\n\t.reg .b32 ra;\n\t"
        "mapa.shared::cluster.u32 ra, %0, %1;\n\t"
        "st.shared::cluster.v4.u32 [ra], {%2, %3, %4, %5};\n\t}"
        :: "r"(laddr), "r"(rank), "r"(v.x), "r"(v.y), "r"(v.z), "r"(v.w) : "memory");
}
__device__ __forceinline__ void cluster_sync() {
    asm volatile("barrier.cluster.arrive.aligned;" ::: "memory");
    asm volatile("barrier.cluster.wait.aligned;" ::: "memory");
}

// ---------------- init ----------------
__global__ void __launch_bounds__(NTHR) init_kernel(
    const float* __restrict__ H0, const float* __restrict__ C0,
    const float* __restrict__ Whq, const float* __restrict__ bq,
    const float* __restrict__ dw, const float* __restrict__ db)
{
    int t = blockIdx.x * blockDim.x + threadIdx.x;
    if (t < HH * BB) {
        int b = t >> 9, h = t & 511;
        g_Hbuf0[t]         = __float2half_rn(H0[t]);   // [b][h]
        g_Cbuf[h * BB + b] = C0[t];
    }
    if (t < HH) {
        float a = 0.f;
        #pragma unroll 8
        for (int e = 0; e < EE; e++) a += Whq[t * EE + e] * dw[e];
        g_weff[t] = a;
    }
    if (t == 0) {
        float a = 0.f;
        for (int e = 0; e < EE; e++) a += bq[e] * dw[e];
        g_beff[0] = a + db[0];
    }
}

// ---------------- prep: Wh images (1024B rows, swizzled fp16) ----------------
// image cidx (0..15): row m = g*32+u (u 0..31), value W_hg[k][cidx*32+u]
__global__ void __launch_bounds__(NTHR) prep_kernel(
    const float* __restrict__ Whi, const float* __restrict__ Whf,
    const float* __restrict__ Who, const float* __restrict__ Whc)
{
    int idx = blockIdx.x * blockDim.x + threadIdx.x;   // 16*128*512 = 1M
    int c = idx >> 16;
    int r = idx & 65535;
    int m = r >> 9;
    int k = r & 511;
    int g = m >> 5, u = m & 31;
    const float* W = (g == 0) ? Whi : (g == 1) ? Whf : (g == 2) ? Who : Whc;
    float v = W[(size_t)k * HH + c * HPC + u];
    uint32_t pos = (uint32_t)m * 1024 + (((uint32_t)k * 2) ^ (((uint32_t)m & 7) << 4));
    *(__half*)(g_Abuf + (size_t)c * A_BYTES + pos) = __float2half_rn(v);
}

// ---------------- prep_x: Wx images (256B rows, swizzled fp16) ---------------
__global__ void __launch_bounds__(NTHR) prep_x_kernel(
    const float* __restrict__ Wxi, const float* __restrict__ Wxf,
    const float* __restrict__ Wxo, const float* __restrict__ Wxc)
{
    int idx = blockIdx.x * blockDim.x + threadIdx.x;   // 16*128*128 = 262144
    int c = idx >> 14;
    int r = idx & 16383;
    int m = r >> 7;
    int k = r & 127;
    int g = m >> 5, u = m & 31;
    const float* W = (g == 0) ? Wxi : (g == 1) ? Wxf : (g == 2) ? Wxo : Wxc;
    float v = W[(size_t)k * HH + c * HPC + u];
    uint32_t pos = (uint32_t)m * 256 + (((uint32_t)k * 2) ^ (((uint32_t)m & 7) << 4));
    *(__half*)(g_Wxbuf + (size_t)c * WX_BYTES + pos) = __float2half_rn(v);
}

// ---------------- persistent recurrence: 8 clusters x 16 CTAs, DSMEM exchange -
__global__ void __launch_bounds__(NTHR, 1) rnn_kernel(
    const int* __restrict__ inputs, const float* __restrict__ emb,
    const float* __restrict__ bi,  const float* __restrict__ bf,
    const float* __restrict__ bo,  const float* __restrict__ bc)
{
    extern __shared__ __align__(16) unsigned char sm[];
    float*  Gsm  = (float*)(sm + G_OFF);
    __half* HnSm = (__half*)(sm + HN_OFF);
    float*  Ysm  = (float*)(sm + YS_OFF);
    const uint32_t smb = smem_u32(sm);
    const uint32_t Ab  = smb;
    const uint32_t WxB = smb + WX_OFF;
    const uint32_t XsB = smb + XS_OFF;

    const int t = threadIdx.x, lane = t & 31, wid = t >> 5;
    const int cta  = blockIdx.x;
    const int grp  = cta >> 4;                 // batch group / cluster 0..7
    const int cidx = (int)cta_rank();          // rank within cluster 0..15
    const int hbase = cidx * HPC;
    const int bbase = grp * NB;

    // load prebuilt Wh image (128 KB) + Wx image (32 KB)
    {
        const float4* asrc = (const float4*)(g_Abuf + (size_t)cidx * A_BYTES);
        float4* adst = (float4*)sm;
        #pragma unroll
        for (int j = 0; j < 32; j++)
            adst[j * 256 + t] = __ldg(&asrc[j * 256 + t]);
        const float4* xsrc = (const float4*)(g_Wxbuf + (size_t)cidx * WX_BYTES);
        float4* xdst = (float4*)(sm + WX_OFF);
        #pragma unroll
        for (int j = 0; j < 8; j++)
            xdst[j * 256 + t] = __ldg(&xsrc[j * 256 + t]);
    }

    // stage initial H slice [8 b][512 h] into buf0 (local, from gmem H0)
    {
        const float4* hs = (const float4*)g_Hbuf0 + bbase * 64;
        #pragma unroll
        for (int j = 0; j < 2; j++) {
            int i16 = j * 256 + t;
            float4 v = hs[i16];
            uint32_t b   = (uint32_t)i16 >> 6;
            uint32_t c16 = (uint32_t)i16 & 63;
            *(float4*)(sm + B0_OFF + b * 1024 + ((c16 * 16) ^ ((b & 7) << 4))) = v;
        }
    }

    // GEMM lane mapping: warp slot mt = wid (0..7): M 16-rows x N 8-cols
    const int q = lane >> 3, r8 = lane & 7;
    const int mt = wid;
    const int arow = mt * 16 + r8 + ((q & 1) << 3);
    const uint32_t acol   = (uint32_t)(q >> 1) * 16;
    const uint32_t aBase  = Ab  + (uint32_t)arow * 1024;
    const uint32_t aBaseX = WxB + (uint32_t)arow * 256;
    const uint32_t axor   = ((uint32_t)arow & 7) << 4;
    const int l16 = lane & 15;
    const int brow = l16 & 7;
    const uint32_t bcol   = (uint32_t)(l16 >> 3) * 16;
    const uint32_t bRow1024 = (uint32_t)brow * 1024;
    const uint32_t bBaseX = XsB + (uint32_t)brow * 256;
    const uint32_t bxor   = ((uint32_t)brow & 7) << 4;

    // epilogue role: 1 cell per thread: h = hbase+u (u 0..31), b = bbase+eb (eb 0..7)
    const int u = t >> 3, eb = t & 7;
    float Cr = g_Cbuf[(hbase + u) * BB + bbase + eb];
    const float wef  = g_weff[hbase + u];
    const float bi_r = __ldg(&bi[hbase + u]);
    const float bf_r = __ldg(&bf[hbase + u]);
    const float bo_r = __ldg(&bo[hbase + u]);
    const float bc_r = __ldg(&bc[hbase + u]);

    // X-gather role: 8 rows x 32 parts (4 floats each)
    const int bqi = t >> 5, part = t & 31;
    const int* tok_ptr = inputs + (bbase + bqi) * SS;
    float4 xpre;
    {
        int tok0 = __ldg(tok_ptr);
        xpre = __ldg((const float4*)(emb + (size_t)tok0 * EE) + part);
    }
    int tok1 = __ldg(tok_ptr + 1);

    __syncthreads();
    cluster_sync();   // all CTAs staged before anyone's DSMEM writes could land

    for (int step = 0; step < SS; step++) {
        const uint32_t Bcur  = smb + ((step & 1) ? B1_OFF : B0_OFF);
        const uint32_t Bnext = smb + ((step & 1) ? B0_OFF : B1_OFF);

        // (1) store prefetched X (fp32 regs -> fp16 swizzled smem, 8B each)
        {
            __half2 h0 = __floats2half2_rn(xpre.x, xpre.y);
            __half2 h1 = __floats2half2_rn(xpre.z, xpre.w);
            uint2 u0 = make_uint2(*(uint32_t*)&h0, *(uint32_t*)&h1);
            uint32_t xo = ((uint32_t)bqi & 7) << 4;
            *(uint2*)(sm + XS_OFF + bqi * 256 + (((uint32_t)part * 8) ^ xo)) = u0;
        }
        // (2) X prefetch for step+1
        if (step + 1 < SS) {
            xpre = __ldg((const float4*)(emb + (size_t)tok1 * EE) + part);
            if (step + 2 < SS) tok1 = __ldg(tok_ptr + step + 2);
        }
        __syncthreads();

        // (3) GEMM: 8 X k-slices + 32 H k-slices, dual accumulators
        float dA[4] = {0.f, 0.f, 0.f, 0.f};
        float dB[4] = {0.f, 0.f, 0.f, 0.f};
        #pragma unroll
        for (int ks = 0; ks < 8; ks += 2) {
            uint32_t a0[4], b0[2], a1[4], b1[2];
            ldsm4(a0, aBaseX + (((uint32_t)ks * 32 + acol) ^ axor));
            ldsm2(b0, bBaseX + (((uint32_t)ks * 32 + bcol) ^ bxor));
            ldsm4(a1, aBaseX + (((uint32_t)(ks + 1) * 32 + acol) ^ axor));
            ldsm2(b1, bBaseX + (((uint32_t)(ks + 1) * 32 + bcol) ^ bxor));
            mma16816(dA, a0, b0);
            mma16816(dB, a1, b1);
        }
        const uint32_t bBaseH = Bcur + bRow1024;
        #pragma unroll 8
        for (int ks = 0; ks < 32; ks += 2) {
            uint32_t a0[4], b0[2], a1[4], b1[2];
            ldsm4(a0, aBase + (((uint32_t)ks * 32 + acol) ^ axor));
            ldsm2(b0, bBaseH + (((uint32_t)ks * 32 + bcol) ^ bxor));
            ldsm4(a1, aBase + (((uint32_t)(ks + 1) * 32 + acol) ^ axor));
            ldsm2(b1, bBaseH + (((uint32_t)(ks + 1) * 32 + bcol) ^ bxor));
            mma16816(dA, a0, b0);
            mma16816(dB, a1, b1);
        }
        {
            int g4 = lane >> 2, t4 = lane & 3;
            int mrow = mt * 16 + g4, nc = 2 * t4;
            *(float2*)&Gsm[mrow * 10 + nc]       = make_float2(dA[0] + dB[0], dA[1] + dB[1]);
            *(float2*)&Gsm[(mrow + 8) * 10 + nc] = make_float2(dA[2] + dB[2], dA[3] + dB[3]);
        }
        __syncthreads();

        // (4) epilogue: 1 cell per thread
        {
            float pi = bi_r + Gsm[(  0 + u) * 10 + eb];
            float pf = bf_r + Gsm[( 32 + u) * 10 + eb];
            float po = bo_r + Gsm[( 64 + u) * 10 + eb];
            float pc = bc_r + Gsm[( 96 + u) * 10 + eb];
            float I = sigf(pi), F = sigf(pf), O = sigf(po), Ct = tanhf_(pc);
            Cr = F * Cr + I * Ct;
            float Hn = O * tanhf_(Cr);
            HnSm[eb * 40 + u] = __float2half_rn(Hn);
            Ysm[u * 10 + eb]  = Hn * wef;
            if (step == SS - 1) {
                g_Hfin[(hbase + u) * BB + bbase + eb] = Hn;
                g_Cbuf[(hbase + u) * BB + bbase + eb] = Cr;
            }
        }
        __syncthreads();

        // (5) DSMEM scatter: our 512B Hn slice -> all 16 peers' Bnext, + Y partial
        if (step + 1 < SS) {
            const uint32_t hb2 = (uint32_t)hbase * 2;   // 16B-aligned (64*cidx)
            #pragma unroll
            for (int rep = 0; rep < 2; rep++) {
                int idx  = t + rep * 256;           // 0..511
                int peer = idx & 15;
                int c    = (idx >> 4) & 3;
                int b    = idx >> 6;                // 0..7
                uint4 v = *(const uint4*)(sm + HN_OFF + b * 80 + c * 16);
                uint32_t dst = Bnext + (uint32_t)b * 1024
                             + ((hb2 + (uint32_t)c * 16) ^ (((uint32_t)b & 7) << 4));
                dsmem_st16(dst, (uint32_t)peer, v);
            }
        }
        if (t < NB) {
            float y = 0.f;
            #pragma unroll
            for (int uu = 0; uu < HPC; uu++) y += Ysm[uu * 10 + t];
            g_party[(size_t)cta * (SS * NB) + (size_t)step * NB + t] = y;
        }

        // (6) HW cluster barrier: orders DSMEM writes, syncs the group
        cluster_sync();
    }
}

// ---------------- finalize ----------------------------------------------------
__global__ void __launch_bounds__(NTHR) fin_kernel(float* __restrict__ out, int out_size)
{
    int blk = blockIdx.x, t = threadIdx.x;
    if (blk < SS) {
        if (t < BB) {
            int g = t >> 3, bw = t & 7;
            float y = g_beff[0];
            #pragma unroll
            for (int c = 0; c < NCG; c++)
                y += g_party[(size_t)(g * NCG + c) * (SS * NB) + (size_t)blk * NB + bw];
            int o = blk * BB + t;
            if (o < out_size) out[o] = y;
        }
    } else {
        if (out_size < SS * BB + 2 * HH * BB) return;
        int i = (blk - SS) * NTHR + t;
        if (i < HH * BB) {
            int h = i >> 6, b = i & 63;
            out[SS * BB + b * HH + h] = g_Hfin[i];
        } else {
            int j = i - HH * BB;
            int h = j >> 6, b = j & 63;
            out[SS * BB + HH * BB + b * HH + h] = g_Cbuf[j];
        }
    }
}

// ---------------- launch ------------------------------------------------------
extern "C" void kernel_launch(void* const* d_in, const int* in_sizes, int n_in,
                              void* d_out, int out_size)
{
    const int*   inputs = (const int*)d_in[0];
    const float* H0  = (const float*)d_in[1];
    const float* C0  = (const float*)d_in[2];
    const float* emb = (const float*)d_in[3];
    const float* Wxi = (const float*)d_in[4];
    const float* Whi = (const float*)d_in[5];
    const float* bi  = (const float*)d_in[6];
    const float* Wxf = (const float*)d_in[7];
    const float* Whf = (const float*)d_in[8];
    const float* bf  = (const float*)d_in[9];
    const float* Wxo = (const float*)d_in[10];
    const float* Who = (const float*)d_in[11];
    const float* bo  = (const float*)d_in[12];
    const float* Wxc = (const float*)d_in[13];
    const float* Whc = (const float*)d_in[14];
    const float* bc  = (const float*)d_in[15];
    const float* Whq = (const float*)d_in[16];
    const float* bq  = (const float*)d_in[17];
    const float* dw  = (const float*)d_in[18];
    const float* db  = (const float*)d_in[19];
    float* out = (float*)d_out;

    cudaFuncSetAttribute(rnn_kernel, cudaFuncAttributeMaxDynamicSharedMemorySize, RNN_SMEM);
    cudaFuncSetAttribute(rnn_kernel, cudaFuncAttributeNonPortableClusterSizeAllowed, 1);

    init_kernel<<<128, NTHR>>>(H0, C0, Whq, bq, dw, db);
    prep_kernel<<<(NCG * MRR * HH) / NTHR, NTHR>>>(Whi, Whf, Who, Whc);
    prep_x_kernel<<<(NCG * MRR * EE) / NTHR, NTHR>>>(Wxi, Wxf, Wxo, Wxc);

    {
        cudaLaunchConfig_t cfg = {};
        cfg.gridDim  = dim3(NGRP * NCG, 1, 1);
        cfg.blockDim = dim3(NTHR, 1, 1);
        cfg.dynamicSmemBytes = RNN_SMEM;
        cudaLaunchAttribute attrs[1];
        attrs[0].id = cudaLaunchAttributeClusterDimension;
        attrs[0].val.clusterDim.x = NCG;
        attrs[0].val.clusterDim.y = 1;
        attrs[0].val.clusterDim.z = 1;
        cfg.attrs = attrs;
        cfg.numAttrs = 1;
        cudaLaunchKernelEx(&cfg, rnn_kernel, inputs, emb, bi, bf, bo, bc);
    }

    fin_kernel<<<SS + (2 * HH * BB) / NTHR, NTHR>>>(out, out_size);
}